// round 17
// baseline (speedup 1.0000x reference)
#include <cuda_runtime.h>
#include <cuda_fp16.h>
#include <cstddef>

#define NMAX 100000
#define EMAX 1600000
#define FDIM 128
#define READY_BIT 0x40000000

// ---------------- static scratch (no allocs allowed) ----------------
__device__ float    g_rowsum[NMAX];       // rowsum of adj .* P (UNnormalized)
__device__ int      g_count[NMAX];        // row degree
__device__ int      g_off[NMAX + 1];      // CSR offsets
__device__ int      g_flag[1024];         // scan aggregate flags (READY_BIT | total)
__device__ float    g_feat1[NMAX];
__device__ float    g_feat2[NMAX];
__device__ float    g_ev[EMAX];           // exp(leaky(e)) per edge (COO order)
__device__ unsigned short g_rank[EMAX];   // within-row rank of each edge
__device__ int2     g_cu[EMAX];           // CSR interleaved (col*32, UNnorm ex-bits)
__device__ __align__(256) __half g_xh[(size_t)NMAX * FDIM];  // fp16 copy of x
__device__ __align__(256) __half g_hA[(size_t)NMAX * FDIM];  // fp16 update hop1
__device__ __align__(256) __half g_hB[(size_t)NMAX * FDIM];  // fp16 update hop2

// ---------------- kernels ----------------

// feat1/feat2 dot products + fused x->fp16 conversion + per-row state init.
__global__ void k_feats(const float* __restrict__ x, const float* __restrict__ a, int n) {
    int gw = (blockIdx.x * blockDim.x + threadIdx.x) >> 5;
    int lane = threadIdx.x & 31;
    if (gw >= n) return;
    float4 v  = __ldg((const float4*)(x + (size_t)gw * FDIM) + lane);
    float4 a1 = __ldg((const float4*)a + lane);
    float4 a2 = __ldg((const float4*)(a + FDIM) + lane);

    __half2 h0 = __floats2half2_rn(v.x, v.y);
    __half2 h1 = __floats2half2_rn(v.z, v.w);
    uint2 packed;
    packed.x = *(unsigned*)&h0;
    packed.y = *(unsigned*)&h1;
    ((uint2*)g_xh)[(size_t)gw * 32 + lane] = packed;

    float d1 = v.x * a1.x + v.y * a1.y + v.z * a1.z + v.w * a1.w;
    float d2 = v.x * a2.x + v.y * a2.y + v.z * a2.z + v.w * a2.w;
    #pragma unroll
    for (int o = 16; o; o >>= 1) {
        d1 += __shfl_down_sync(0xffffffffu, d1, o);
        d2 += __shfl_down_sync(0xffffffffu, d2, o);
    }
    if (lane == 0) {
        g_feat1[gw] = d1; g_feat2[gw] = d2;
        g_rowsum[gw] = 0.f; g_count[gw] = 0;
        if (gw < 1024) g_flag[gw] = 0;
    }
}

__device__ __forceinline__ float edge_ex(int r, int c) {
    float ev = __ldg(&g_feat1[r]) + __ldg(&g_feat2[c]);
    ev = (ev >= 0.f) ? ev : 0.2f * ev;
    return __expf(ev);
}

// edge pass: 4 edges/thread (int4/float4 coalesced loads, 4 independent chains)
__global__ void k_edge1(const int* __restrict__ row, const int* __restrict__ col,
                        const float* __restrict__ adj, int e) {
    int i = blockIdx.x * blockDim.x + threadIdx.x;
    int e4 = e >> 2;
    if (i < e4) {
        int4   r4 = __ldg((const int4*)row + i);
        int4   c4 = __ldg((const int4*)col + i);
        float4 a4 = __ldg((const float4*)adj + i);
        float ex0 = edge_ex(r4.x, c4.x);
        float ex1 = edge_ex(r4.y, c4.y);
        float ex2 = edge_ex(r4.z, c4.z);
        float ex3 = edge_ex(r4.w, c4.w);
        ((float4*)g_ev)[i] = make_float4(ex0, ex1, ex2, ex3);
        atomicAdd(&g_rowsum[r4.x], 0.5f * a4.x * ex0);
        atomicAdd(&g_rowsum[r4.y], 0.5f * a4.y * ex1);
        atomicAdd(&g_rowsum[r4.z], 0.5f * a4.z * ex2);
        atomicAdd(&g_rowsum[r4.w], 0.5f * a4.w * ex3);
        int k0 = atomicAdd(&g_count[r4.x], 1);
        int k1 = atomicAdd(&g_count[r4.y], 1);
        int k2 = atomicAdd(&g_count[r4.z], 1);
        int k3 = atomicAdd(&g_count[r4.w], 1);
        ushort4 rk;
        rk.x = (unsigned short)k0; rk.y = (unsigned short)k1;
        rk.z = (unsigned short)k2; rk.w = (unsigned short)k3;
        ((ushort4*)g_rank)[i] = rk;
    }
    if (i == 0) {                                   // scalar tail (<=3 edges)
        for (int j = e & ~3; j < e; j++) {
            int r = row[j];
            float ex = edge_ex(r, col[j]);
            g_ev[j] = ex;
            atomicAdd(&g_rowsum[r], 0.5f * adj[j] * ex);
            g_rank[j] = (unsigned short)atomicAdd(&g_count[r], 1);
        }
    }
}

// single-kernel scan: per-block shuffle scan + decoupled aggregate lookback.
__global__ void k_scan(int nb, int n) {
    __shared__ int warp_tot[32];
    __shared__ int s_prefix;
    int b = blockIdx.x;
    int i = b * 1024 + threadIdx.x;
    int lane = threadIdx.x & 31, wid = threadIdx.x >> 5;
    int v = (i < n) ? g_count[i] : 0;
    int s = v;
    #pragma unroll
    for (int o = 1; o < 32; o <<= 1) {
        int t = __shfl_up_sync(0xffffffffu, s, o);
        if (lane >= o) s += t;
    }
    if (lane == 31) warp_tot[wid] = s;
    __syncthreads();
    if (wid == 0) {
        int w = warp_tot[lane];
        #pragma unroll
        for (int o = 1; o < 32; o <<= 1) {
            int t = __shfl_up_sync(0xffffffffu, w, o);
            if (lane >= o) w += t;
        }
        warp_tot[lane] = w;
    }
    __syncthreads();
    int base = wid ? warp_tot[wid - 1] : 0;
    int block_tot = warp_tot[31];
    if (threadIdx.x == 0) {
        atomicExch(&g_flag[b], block_tot | READY_BIT);
        s_prefix = 0;
    }
    __syncthreads();
    if (threadIdx.x < 32) {
        int acc = 0;
        for (int p = lane; p < b; p += 32) {
            int f;
            do { f = atomicAdd(&g_flag[p], 0); } while (!(f & READY_BIT));
            acc += f & (READY_BIT - 1);
        }
        #pragma unroll
        for (int o = 16; o; o >>= 1) acc += __shfl_down_sync(0xffffffffu, acc, o);
        if (lane == 0) s_prefix = acc;
    }
    __syncthreads();
    int prefix = s_prefix;
    if (i < n) g_off[i] = prefix + base + s - v;           // exclusive
    if (b == nb - 1 && threadIdx.x == 0) g_off[n] = prefix + block_tot;
}

// scatter: 4 edges/thread, coalesced loads, 4 independent scattered chains.
__global__ void k_scatter(const int* __restrict__ row, const int* __restrict__ col, int e) {
    int i = blockIdx.x * blockDim.x + threadIdx.x;
    int e4 = e >> 2;
    if (i < e4) {
        int4    r4  = __ldg((const int4*)row + i);
        int4    c4  = __ldg((const int4*)col + i);
        float4  ev4 = __ldg((const float4*)g_ev + i);
        ushort4 rk4 = ((const ushort4*)g_rank)[i];
        int p0 = __ldg(&g_off[r4.x]) + (int)rk4.x;
        int p1 = __ldg(&g_off[r4.y]) + (int)rk4.y;
        int p2 = __ldg(&g_off[r4.z]) + (int)rk4.z;
        int p3 = __ldg(&g_off[r4.w]) + (int)rk4.w;
        g_cu[p0] = make_int2(c4.x * 32, __float_as_int(ev4.x));
        g_cu[p1] = make_int2(c4.y * 32, __float_as_int(ev4.y));
        g_cu[p2] = make_int2(c4.z * 32, __float_as_int(ev4.z));
        g_cu[p3] = make_int2(c4.w * 32, __float_as_int(ev4.w));
    }
    if (i == 0) {                                   // scalar tail (<=3 edges)
        for (int j = e & ~3; j < e; j++) {
            int pos = __ldg(&g_off[row[j]]) + (int)g_rank[j];
            g_cu[pos] = make_int2(col[j] * 32, __float_as_int(g_ev[j]));
        }
    }
}

// ---- SpMM ---- (R16-proven; FROZEN — at effective L2 roofline)
template <int STEP>
__global__ void __launch_bounds__(256) k_spmm(float* __restrict__ out,
                                              const float* __restrict__ cheb, int n) {
    __shared__ int2 s_cu[8][64];
    int wip  = threadIdx.x >> 5;
    int warp = (blockIdx.x * 256 + threadIdx.x) >> 5;
    int lane = threadIdx.x & 31;
    int r0 = warp * 2;
    if (r0 >= n) return;
    bool has2 = (r0 + 1 < n);

    const uint2* in_upd = (STEP == 0) ? (const uint2*)g_xh
                        : (STEP == 1) ? (const uint2*)g_hA : (const uint2*)g_hB;

    int o0 = __ldg(&g_off[r0]);
    int o1 = __ldg(&g_off[r0 + 1]);
    int o2 = has2 ? __ldg(&g_off[r0 + 2]) : o1;
    int deg0 = o1 - o0;
    int deg1 = o2 - o1;
    int2 cu0 = make_int2(0, 0), cu1 = make_int2(0, 0);
    if (lane < deg0) cu0 = __ldg(&g_cu[o0 + lane]);
    if (lane < deg1) cu1 = __ldg(&g_cu[o1 + lane]);
    s_cu[wip][lane]      = cu0;
    s_cu[wip][32 + lane] = cu1;
    __syncwarp();

    float c0 = 0.f, c1 = 0.f;
    if (STEP == 2) {
        c0 = 1.f / (1.f + __expf(-__ldg(&cheb[0])));
        c1 = 1.f / (1.f + __expf(-__ldg(&cheb[1])));
    }

    #pragma unroll
    for (int rr = 0; rr < 2; rr++) {
        int r   = r0 + rr;
        if (rr == 1 && !has2) break;
        int beg = rr ? o1 : o0;
        int deg = rr ? deg1 : deg0;

        float4 acc = make_float4(0.f, 0.f, 0.f, 0.f);
        float s = 0.f;
        int m = min(32, deg);
        const int2* tile = &s_cu[wip][rr * 32];
        #pragma unroll 8
        for (int t = 0; t < m; t++) {
            int2 cu = tile[t];
            float uu = __int_as_float(cu.y);
            s += uu;
            uint2 raw = __ldg(in_upd + (size_t)(cu.x + lane));
            float2 f0 = __half22float2(*(__half2*)&raw.x);
            float2 f1 = __half22float2(*(__half2*)&raw.y);
            acc.x += uu * f0.x;
            acc.y += uu * f0.y;
            acc.z += uu * f1.x;
            acc.w += uu * f1.y;
        }
        for (int j0 = 32; j0 < deg; j0 += 32) {     // rare: degree > 32
            int2 cu = make_int2(0, 0);
            if (j0 + lane < deg) cu = __ldg(&g_cu[beg + j0 + lane]);
            int mm = min(32, deg - j0);
            for (int t = 0; t < mm; t++) {
                int   cc = __shfl_sync(0xffffffffu, cu.x, t);
                float uu = __int_as_float(__shfl_sync(0xffffffffu, cu.y, t));
                s += uu;
                uint2 raw = __ldg(in_upd + (size_t)(cc + lane));
                float2 f0 = __half22float2(*(__half2*)&raw.x);
                float2 f1 = __half22float2(*(__half2*)&raw.y);
                acc.x += uu * f0.x;
                acc.y += uu * f0.y;
                acc.z += uu * f1.x;
                acc.w += uu * f1.y;
            }
        }

        float inv_s = (s > 0.f) ? 1.f / s : 0.f;
        acc.x *= inv_s; acc.y *= inv_s; acc.z *= inv_s; acc.w *= inv_s;

        size_t v2idx = (size_t)r * 32 + lane;
        if (STEP < 2) {
            __half2 h0 = __floats2half2_rn(acc.x, acc.y);
            __half2 h1 = __floats2half2_rn(acc.z, acc.w);
            uint2 packed;
            packed.x = *(unsigned*)&h0;
            packed.y = *(unsigned*)&h1;
            ((uint2*)(STEP == 0 ? g_hA : g_hB))[v2idx] = packed;
        } else {
            float rs0 = __ldg(&g_rowsum[r]) * inv_s;
            float rs1 = rs0 * c0;
            float rs2 = rs1 * c1;
            float w0 = 0.009f * (1.f - 0.9f * rs0);
            float w1 = 0.09f  * (1.f - 0.9f * rs1);
            float w2 = 0.9f   * (1.f - 0.9f * rs2);

            uint2 rawx = ((const uint2*)g_xh)[v2idx];
            uint2 rawa = ((const uint2*)g_hA)[v2idx];
            uint2 rawb = ((const uint2*)g_hB)[v2idx];
            float2 x0 = __half22float2(*(__half2*)&rawx.x);
            float2 x1 = __half22float2(*(__half2*)&rawx.y);
            float2 a0 = __half22float2(*(__half2*)&rawa.x);
            float2 a1 = __half22float2(*(__half2*)&rawa.y);
            float2 b0 = __half22float2(*(__half2*)&rawb.x);
            float2 b1 = __half22float2(*(__half2*)&rawb.y);
            float4 o;
            o.x = 0.001f * x0.x + w0 * a0.x + w1 * b0.x + w2 * acc.x;
            o.y = 0.001f * x0.y + w0 * a0.y + w1 * b0.y + w2 * acc.y;
            o.z = 0.001f * x1.x + w0 * a1.x + w1 * b1.x + w2 * acc.z;
            o.w = 0.001f * x1.y + w0 * a1.y + w1 * b1.y + w2 * acc.w;
            ((float4*)out)[(size_t)r * (FDIM / 4) + lane] = o;
        }
    }
}

// ---------------- launch ----------------
extern "C" void kernel_launch(void* const* d_in, const int* in_sizes, int n_in,
                              void* d_out, int out_size) {
    const float* x    = (const float*)d_in[0];
    const float* a    = (const float*)d_in[2];
    const float* cheb = (const float*)d_in[4];
    const float* adj  = (const float*)d_in[5];
    const int*   row  = (const int*)d_in[6];
    const int*   col  = (const int*)d_in[7];
    float* out = (float*)d_out;

    int n = in_sizes[0] / FDIM;
    int e = in_sizes[5];

    k_feats<<<((size_t)n * 32 + 255) / 256, 256>>>(x, a, n);

    int e4 = e >> 2;
    k_edge1<<<(e4 + 255) / 256, 256>>>(row, col, adj, e);

    int nb = (n + 1023) / 1024;
    k_scan<<<nb, 1024>>>(nb, n);

    k_scatter<<<(e4 + 255) / 256, 256>>>(row, col, e);

    int spmm_blocks = (n + 15) / 16;   // 8 warps/block, 2 rows/warp
    k_spmm<0><<<spmm_blocks, 256>>>(out, cheb, n);
    k_spmm<1><<<spmm_blocks, 256>>>(out, cheb, n);
    k_spmm<2><<<spmm_blocks, 256>>>(out, cheb, n);
}